// round 8
// baseline (speedup 1.0000x reference)
#include <cuda_runtime.h>
#include <math.h>

#define H_IMG 256
#define W_IMG 256
#define TILE 8
#define NTX 32
#define NTILES 1024
#define TANFOV 0.7f
#define MAXG 512

__device__ float4 g_p1v[MAXG];               // mx, my, 0.5*conicA, conicB
__device__ float4 g_p2v[MAXG];               // 0.5*conicC, opacity, z, +ln(255*op)
__device__ float4 g_clv[MAXG];               // r, g, b, 0
__device__ unsigned g_trv[MAXG];             // tile range x0|x1<<8|y0<<16|y1<<24
__device__ unsigned long long g_keyv[MAXG];  // (float_bits(z)<<32)|idx
__device__ int g_cnt[NTILES];
__device__ unsigned long long g_list[NTILES * MAXG];

__global__ __launch_bounds__(64) void gs_pre(
    const float* __restrict__ means,
    const float* __restrict__ opac,
    const float* __restrict__ colors,
    const float* __restrict__ scales,
    const float* __restrict__ rots,
    const float* __restrict__ vm,
    float* __restrict__ radii_out, int n)
{
    const int i = blockIdx.x * 64 + threadIdx.x;
    const int nthr = gridDim.x * 64;
    for (int j = i; j < NTILES; j += nthr) g_cnt[j] = 0;   // reset bins each launch
    if (i >= n) return;

    const float fx = W_IMG / (2.0f * TANFOV);
    const float fy = H_IMG / (2.0f * TANFOV);
    const float R00 = vm[0], R01 = vm[1], R02 = vm[2],  t0 = vm[3];
    const float R10 = vm[4], R11 = vm[5], R12 = vm[6],  t1 = vm[7];
    const float R20 = vm[8], R21 = vm[9], R22 = vm[10], t2 = vm[11];

    float m0 = means[3*i], m1 = means[3*i+1], m2 = means[3*i+2];
    float pxv = R00*m0 + R01*m1 + R02*m2 + t0;
    float pyv = R10*m0 + R11*m1 + R12*m2 + t1;
    float zg  = R20*m0 + R21*m1 + R22*m2 + t2;
    float zc = fmaxf(zg, 1e-4f);
    float lim = 1.3f * TANFOV;
    float txc = fminf(fmaxf(pxv/zc, -lim), lim) * zc;
    float tyc = fminf(fmaxf(pyv/zc, -lim), lim) * zc;

    float q0 = rots[4*i], q1 = rots[4*i+1], q2 = rots[4*i+2], q3 = rots[4*i+3];
    float qn = rsqrtf(q0*q0 + q1*q1 + q2*q2 + q3*q3);
    q0 *= qn; q1 *= qn; q2 *= qn; q3 *= qn;
    float xx = q1*q1, yy = q2*q2, zz = q3*q3;
    float xy = q1*q2, xz = q1*q3, yz = q2*q3;
    float rx = q0*q1, ry = q0*q2, rz = q0*q3;
    float Q00 = 1.f-2.f*(yy+zz), Q01 = 2.f*(xy-rz),     Q02 = 2.f*(xz+ry);
    float Q10 = 2.f*(xy+rz),     Q11 = 1.f-2.f*(xx+zz), Q12 = 2.f*(yz-rx);
    float Q20 = 2.f*(xz-ry),     Q21 = 2.f*(yz+rx),     Q22 = 1.f-2.f*(xx+yy);
    float sx = scales[3*i], sy = scales[3*i+1], sz2 = scales[3*i+2];
    float M00 = Q00*sx, M01 = Q01*sy, M02 = Q02*sz2;
    float M10 = Q10*sx, M11 = Q11*sy, M12 = Q12*sz2;
    float M20 = Q20*sx, M21 = Q21*sy, M22 = Q22*sz2;
    float C00 = M00*M00 + M01*M01 + M02*M02;
    float C01 = M00*M10 + M01*M11 + M02*M12;
    float C02 = M00*M20 + M01*M21 + M02*M22;
    float C11 = M10*M10 + M11*M11 + M12*M12;
    float C12 = M10*M20 + M11*M21 + M12*M22;
    float C22 = M20*M20 + M21*M21 + M22*M22;
    float j00 = fx/zc, j02 = -fx*txc/(zc*zc);
    float j11 = fy/zc, j12 = -fy*tyc/(zc*zc);
    float T00 = j00*R00 + j02*R20, T01 = j00*R01 + j02*R21, T02 = j00*R02 + j02*R22;
    float T10 = j11*R10 + j12*R20, T11 = j11*R11 + j12*R21, T12 = j11*R12 + j12*R22;
    float u0 = C00*T00 + C01*T01 + C02*T02;
    float u1 = C01*T00 + C11*T01 + C12*T02;
    float u2 = C02*T00 + C12*T01 + C22*T02;
    float v0 = C00*T10 + C01*T11 + C02*T12;
    float v1 = C01*T10 + C11*T11 + C12*T12;
    float v2 = C02*T10 + C12*T11 + C22*T12;
    float a  = T00*u0 + T01*u1 + T02*u2 + 0.3f;
    float bq = T10*u0 + T11*u1 + T12*u2;
    float c  = T10*v0 + T11*v1 + T12*v2 + 0.3f;
    float det = a*c - bq*bq;
    float inv_det = 1.0f / fmaxf(det, 1e-12f);
    float cA = c*inv_det, cB = -bq*inv_det, cC = a*inv_det;
    float mid = 0.5f*(a + c);
    float lam1 = mid + sqrtf(fmaxf(mid*mid - det, 0.1f));
    radii_out[i] = ceilf(3.0f * sqrtf(lam1));
    float mx = fx*pxv/zc + 0.5f*W_IMG - 0.5f;
    float my = fy*pyv/zc + 0.5f*H_IMG - 0.5f;
    bool valid = (zg > 0.2f) && (det > 0.0f);
    float op = opac[i];
    float pln = logf(255.0f * op);             // keep: 0 <= m <= pln

    unsigned tr = 0x000000FFu;                 // empty: x0=255 > x1=0
    if (valid && pln > 0.0f) {
        float sthr = 2.0f * pln;
        float hx = sqrtf(sthr * a) * 1.001f + 0.6f;
        float hy = sqrtf(sthr * c) * 1.001f + 0.6f;
        bool nonempty = (mx + hx >= 0.f) && (mx - hx <= 255.f) &&
                        (my + hy >= 0.f) && (my - hy <= 255.f);
        if (nonempty) {
            float x0f = fminf(fmaxf(floorf((mx - hx) * 0.125f), 0.f), 31.f);
            float x1f = fminf(fmaxf(floorf((mx + hx) * 0.125f), 0.f), 31.f);
            float y0f = fminf(fmaxf(floorf((my - hy) * 0.125f), 0.f), 31.f);
            float y1f = fminf(fmaxf(floorf((my + hy) * 0.125f), 0.f), 31.f);
            tr = (unsigned)x0f | ((unsigned)x1f << 8) |
                 ((unsigned)y0f << 16) | ((unsigned)y1f << 24);
        }
    }
    g_trv[i]  = tr;
    g_p1v[i]  = make_float4(mx, my, 0.5f * cA, cB);
    g_p2v[i]  = make_float4(0.5f * cC, op, zg, pln);
    g_clv[i]  = make_float4(colors[3*i], colors[3*i+1], colors[3*i+2], 0.0f);
    g_keyv[i] = ((unsigned long long)__float_as_uint(zg) << 32) | (unsigned)i;
}

// Bin gaussians into per-tile lists (unsorted; raster re-ranks by key)
__global__ __launch_bounds__(256) void gs_bin(int n)
{
    const int i = blockIdx.x * 256 + threadIdx.x;
    if (i >= n) return;
    unsigned tr = g_trv[i];
    int x0 = tr & 255, x1 = (tr >> 8) & 255;
    int y0 = (tr >> 16) & 255, y1 = tr >> 24;
    unsigned long long key = g_keyv[i];
    for (int ty = y0; ty <= y1; ty++) {
        for (int tx = x0; tx <= x1; tx++) {
            int t = ty * NTX + tx;
            int pos = atomicAdd(&g_cnt[t], 1);
            g_list[t * MAXG + pos] = key;
        }
    }
}

__global__ __launch_bounds__(256) void gs_raster(
    const float* __restrict__ bg, float* __restrict__ out, int n)
{
    __shared__ float4 sP1[MAXG + 4];
    __shared__ float4 sP2[MAXG + 4];
    __shared__ float4 sCl[MAXG + 4];
    __shared__ unsigned long long sKey[MAXG];

    const int tid  = threadIdx.x;
    const int lane = tid & 31;
    const int seg = tid & 3;
    const int p   = tid >> 2;                  // 0..63
    const int bx = blockIdx.x & (NTX - 1), by = blockIdx.x >> 5;
    const int t  = blockIdx.x;
    const int px = bx * TILE + (p & (TILE - 1));
    const int py = by * TILE + (p / TILE);
    const float bgr = bg[0], bgg = bg[1], bgb = bg[2];
    const int HW = H_IMG * W_IMG;
    const int pix = py * W_IMG + px;

    const int k = g_cnt[t];

    if (k == 0) {                              // empty tile fast path
        if (seg == 0) {
            out[3 * pix + 0] = bgr;
            out[3 * pix + 1] = bgg;
            out[3 * pix + 2] = bgb;
            float* o2 = out + 3 * HW + n;
            o2[pix] = 0.0f; o2[HW + pix] = 0.0f;
            o2[2 * HW + pix] = 0.0f; o2[3 * HW + pix] = 0.0f;
        }
        return;
    }

    // load keys for this tile
    for (int e = tid; e < k; e += 256) sKey[e] = g_list[t * MAXG + e];
    __syncthreads();

    // stable z-rank via unique u64 keys; record LDGs overlap rank loop
    for (int e = tid; e < k; e += 256) {
        unsigned long long key = sKey[e];
        int ie = (int)(unsigned)(key & 0xffffffffu);
        float4 a = g_p1v[ie];
        float4 b = g_p2v[ie];
        float4 c = g_clv[ie];
        int r = 0;
        #pragma unroll 4
        for (int j = 0; j < k; j++) r += (sKey[j] < key) ? 1 : 0;
        sP1[r] = a; sP2[r] = b; sCl[r] = c;
    }
    if (tid < 3) {
        sP1[k + tid] = make_float4(0.f, 0.f, 0.f, 0.f);
        sP2[k + tid] = make_float4(0.f, 0.f, 0.f, -1.0f);  // pln<0 -> never kept
        sCl[k + tid] = make_float4(0.f, 0.f, 0.f, 0.f);
    }
    __syncthreads();

    // 4-way segmented compositing
    const float fpx = (float)px, fpy = (float)py;
    float T = 1.0f, aR = 0.f, aG = 0.f, aB = 0.f, dep = 0.f, mw = 0.f;
    int cnt = 0;
    const int q = (k + 3) >> 2;
    const int s0 = seg * q;
    #pragma unroll 2
    for (int j = 0; j < q; j++) {
        int idx = s0 + j;
        float4 p1 = sP1[idx];
        float4 p2 = sP2[idx];
        float dx = fpx - p1.x, dy = fpy - p1.y;
        float m = (p1.z * dx) * dx + (p2.x * dy) * dy + (p1.w * dx) * dy;
        bool kp = (m >= 0.0f) && (m <= p2.w);  // power<=0 && alpha>=1/255
        float al = fminf(0.99f, p2.y * __expf(-m));
        float a_eff = kp ? al : 0.0f;
        float4 c4 = sCl[idx];
        float wv = a_eff * T;
        aR = fmaf(wv, c4.x, aR);
        aG = fmaf(wv, c4.y, aG);
        aB = fmaf(wv, c4.z, aB);
        dep = fmaf(wv, p2.z, dep);
        mw = fmaxf(mw, wv);
        cnt += kp ? 1 : 0;
        T -= wv;
    }

    // merge 4 segment states (adjacent lanes)
    #pragma unroll
    for (int d = 1; d <= 2; d <<= 1) {
        float To = __shfl_xor_sync(0xffffffffu, T,  d);
        float ro = __shfl_xor_sync(0xffffffffu, aR, d);
        float go = __shfl_xor_sync(0xffffffffu, aG, d);
        float bo = __shfl_xor_sync(0xffffffffu, aB, d);
        float do_ = __shfl_xor_sync(0xffffffffu, dep, d);
        float mo = __shfl_xor_sync(0xffffffffu, mw, d);
        int   co = __shfl_xor_sync(0xffffffffu, cnt, d);
        bool rightSelf = (lane & d) != 0;
        float TL = rightSelf ? To : T,   TR = rightSelf ? T   : To;
        float rL = rightSelf ? ro : aR,  rR = rightSelf ? aR  : ro;
        float gL = rightSelf ? go : aG,  gR = rightSelf ? aG  : go;
        float bL = rightSelf ? bo : aB,  bR = rightSelf ? aB  : bo;
        float dL = rightSelf ? do_ : dep, dR = rightSelf ? dep : do_;
        float mL = rightSelf ? mo : mw,  mR = rightSelf ? mw  : mo;
        aR  = fmaf(TL, rR, rL);
        aG  = fmaf(TL, gR, gL);
        aB  = fmaf(TL, bR, bL);
        dep = fmaf(TL, dR, dL);
        mw  = fmaxf(mL, TL * mR);
        T   = TL * TR;
        cnt += co;
    }

    if (seg == 0) {
        out[3 * pix + 0] = aR + T * bgr;
        out[3 * pix + 1] = aG + T * bgg;
        out[3 * pix + 2] = aB + T * bgb;
        float* o2 = out + 3 * HW + n;
        o2[pix]          = (float)cnt;   // out_observe
        o2[HW + pix]     = dep;          // out_plane_depth
        o2[2 * HW + pix] = mw;           // app_opacity
        o2[3 * HW + pix] = 1.0f - T;     // color_alpha
    }
}

extern "C" void kernel_launch(void* const* d_in, const int* in_sizes, int n_in,
                              void* d_out, int out_size) {
    const float* means  = (const float*)d_in[0];
    const float* opac   = (const float*)d_in[1];
    const float* colors = (const float*)d_in[2];
    const float* scales = (const float*)d_in[3];
    const float* rots   = (const float*)d_in[4];
    const float* bg     = (const float*)d_in[5];
    const float* vm     = (const float*)d_in[6];
    const int n = in_sizes[0] / 3;
    float* out = (float*)d_out;

    gs_pre<<<(n + 63) / 64, 64>>>(means, opac, colors, scales, rots, vm,
                                  out + (size_t)3 * H_IMG * W_IMG, n);
    gs_bin<<<(n + 255) / 256, 256>>>(n);
    gs_raster<<<NTILES, 256>>>(bg, out, n);
}

// round 9
// speedup vs baseline: 4.3623x; 4.3623x over previous
#include <cuda_runtime.h>
#include <math.h>

#define H_IMG 256
#define W_IMG 256
#define TILE 8
#define NTX 32
#define NTILES 1024
#define TANFOV 0.7f
#define MAXG 512

__device__ float4 g_p1v[MAXG];               // mx, my, 0.5*conicA, conicB
__device__ float4 g_p2v[MAXG];               // 0.5*conicC, opacity, z, +ln(255*op)
__device__ float4 g_clv[MAXG];               // r, g, b, 0
__device__ int g_cnt[NTILES];                // ALWAYS zero at kernel_launch entry
__device__ unsigned long long g_list[NTILES * MAXG];

__global__ __launch_bounds__(64) void gs_pre(
    const float* __restrict__ means,
    const float* __restrict__ opac,
    const float* __restrict__ colors,
    const float* __restrict__ scales,
    const float* __restrict__ rots,
    const float* __restrict__ vm,
    float* __restrict__ radii_out, int n)
{
    const int i = blockIdx.x * 64 + threadIdx.x;
    const int lane = threadIdx.x & 31;
    const bool act = (i < n);

    const float fx = W_IMG / (2.0f * TANFOV);
    const float fy = H_IMG / (2.0f * TANFOV);
    const float R00 = vm[0], R01 = vm[1], R02 = vm[2],  t0 = vm[3];
    const float R10 = vm[4], R11 = vm[5], R12 = vm[6],  t1 = vm[7];
    const float R20 = vm[8], R21 = vm[9], R22 = vm[10], t2 = vm[11];

    unsigned tr = 0x000000FFu;                 // empty: x0=255 > x1=0
    unsigned long long key = 0ull;

    if (act) {
        float m0 = means[3*i], m1 = means[3*i+1], m2 = means[3*i+2];
        float pxv = R00*m0 + R01*m1 + R02*m2 + t0;
        float pyv = R10*m0 + R11*m1 + R12*m2 + t1;
        float zg  = R20*m0 + R21*m1 + R22*m2 + t2;
        float zc = fmaxf(zg, 1e-4f);
        float lim = 1.3f * TANFOV;
        float txc = fminf(fmaxf(pxv/zc, -lim), lim) * zc;
        float tyc = fminf(fmaxf(pyv/zc, -lim), lim) * zc;

        float q0 = rots[4*i], q1 = rots[4*i+1], q2 = rots[4*i+2], q3 = rots[4*i+3];
        float qn = rsqrtf(q0*q0 + q1*q1 + q2*q2 + q3*q3);
        q0 *= qn; q1 *= qn; q2 *= qn; q3 *= qn;
        float xx = q1*q1, yy = q2*q2, zz = q3*q3;
        float xy = q1*q2, xz = q1*q3, yz = q2*q3;
        float rx = q0*q1, ry = q0*q2, rz = q0*q3;
        float Q00 = 1.f-2.f*(yy+zz), Q01 = 2.f*(xy-rz),     Q02 = 2.f*(xz+ry);
        float Q10 = 2.f*(xy+rz),     Q11 = 1.f-2.f*(xx+zz), Q12 = 2.f*(yz-rx);
        float Q20 = 2.f*(xz-ry),     Q21 = 2.f*(yz+rx),     Q22 = 1.f-2.f*(xx+yy);
        float sx = scales[3*i], sy = scales[3*i+1], sz2 = scales[3*i+2];
        float M00 = Q00*sx, M01 = Q01*sy, M02 = Q02*sz2;
        float M10 = Q10*sx, M11 = Q11*sy, M12 = Q12*sz2;
        float M20 = Q20*sx, M21 = Q21*sy, M22 = Q22*sz2;
        float C00 = M00*M00 + M01*M01 + M02*M02;
        float C01 = M00*M10 + M01*M11 + M02*M12;
        float C02 = M00*M20 + M01*M21 + M02*M22;
        float C11 = M10*M10 + M11*M11 + M12*M12;
        float C12 = M10*M20 + M11*M21 + M12*M22;
        float C22 = M20*M20 + M21*M21 + M22*M22;
        float j00 = fx/zc, j02 = -fx*txc/(zc*zc);
        float j11 = fy/zc, j12 = -fy*tyc/(zc*zc);
        float T00 = j00*R00 + j02*R20, T01 = j00*R01 + j02*R21, T02 = j00*R02 + j02*R22;
        float T10 = j11*R10 + j12*R20, T11 = j11*R11 + j12*R21, T12 = j11*R12 + j12*R22;
        float u0 = C00*T00 + C01*T01 + C02*T02;
        float u1 = C01*T00 + C11*T01 + C12*T02;
        float u2 = C02*T00 + C12*T01 + C22*T02;
        float v0 = C00*T10 + C01*T11 + C02*T12;
        float v1 = C01*T10 + C11*T11 + C12*T12;
        float v2 = C02*T10 + C12*T11 + C22*T12;
        float a  = T00*u0 + T01*u1 + T02*u2 + 0.3f;
        float bq = T10*u0 + T11*u1 + T12*u2;
        float c  = T10*v0 + T11*v1 + T12*v2 + 0.3f;
        float det = a*c - bq*bq;
        float inv_det = 1.0f / fmaxf(det, 1e-12f);
        float cA = c*inv_det, cB = -bq*inv_det, cC = a*inv_det;
        float mid = 0.5f*(a + c);
        float lam1 = mid + sqrtf(fmaxf(mid*mid - det, 0.1f));
        radii_out[i] = ceilf(3.0f * sqrtf(lam1));
        float mx = fx*pxv/zc + 0.5f*W_IMG - 0.5f;
        float my = fy*pyv/zc + 0.5f*H_IMG - 0.5f;
        bool valid = (zg > 0.2f) && (det > 0.0f);
        float op = opac[i];
        float pln = logf(255.0f * op);         // keep: 0 <= m <= pln

        if (valid && pln > 0.0f) {
            float sthr = 2.0f * pln;
            float hx = sqrtf(sthr * a) * 1.001f + 0.6f;
            float hy = sqrtf(sthr * c) * 1.001f + 0.6f;
            bool nonempty = (mx + hx >= 0.f) && (mx - hx <= 255.f) &&
                            (my + hy >= 0.f) && (my - hy <= 255.f);
            if (nonempty) {
                float x0f = fminf(fmaxf(floorf((mx - hx) * 0.125f), 0.f), 31.f);
                float x1f = fminf(fmaxf(floorf((mx + hx) * 0.125f), 0.f), 31.f);
                float y0f = fminf(fmaxf(floorf((my - hy) * 0.125f), 0.f), 31.f);
                float y1f = fminf(fmaxf(floorf((my + hy) * 0.125f), 0.f), 31.f);
                tr = (unsigned)x0f | ((unsigned)x1f << 8) |
                     ((unsigned)y0f << 16) | ((unsigned)y1f << 24);
            }
        }
        g_p1v[i] = make_float4(mx, my, 0.5f * cA, cB);
        g_p2v[i] = make_float4(0.5f * cC, op, zg, pln);
        g_clv[i] = make_float4(colors[3*i], colors[3*i+1], colors[3*i+2], 0.0f);
        key = ((unsigned long long)__float_as_uint(zg) << 32) | (unsigned)i;
    }

    // Warp-cooperative binning: all 32 lanes split each gaussian's tile set.
    #pragma unroll 1
    for (int s = 0; s < 32; s++) {
        unsigned trs = __shfl_sync(0xffffffffu, tr, s);
        unsigned long long ks = __shfl_sync(0xffffffffu, key, s);
        int x0 = trs & 255, x1 = (trs >> 8) & 255;
        int y0 = (trs >> 16) & 255, y1 = (int)(trs >> 24);
        int w = x1 - x0 + 1;
        int cnt = w * (y1 - y0 + 1);
        if (x0 > x1) continue;                 // empty marker
        for (int j = lane; j < cnt; j += 32) {
            int ty = y0 + j / w;
            int tx = x0 + j % w;
            int t = ty * NTX + tx;
            int pos = atomicAdd(&g_cnt[t], 1);
            g_list[t * MAXG + pos] = ks;
        }
    }
}

__global__ __launch_bounds__(256) void gs_raster(
    const float* __restrict__ bg, float* __restrict__ out, int n)
{
    __shared__ float4 sP1[MAXG + 4];
    __shared__ float4 sP2[MAXG + 4];
    __shared__ float4 sCl[MAXG + 4];
    __shared__ unsigned long long sKey[MAXG];

    const int tid  = threadIdx.x;
    const int lane = tid & 31;
    const int seg = tid & 3;
    const int p   = tid >> 2;                  // 0..63
    const int bx = blockIdx.x & (NTX - 1), by = blockIdx.x >> 5;
    const int t  = blockIdx.x;
    const int px = bx * TILE + (p & (TILE - 1));
    const int py = by * TILE + (p / TILE);
    const float bgr = bg[0], bgg = bg[1], bgb = bg[2];
    const int HW = H_IMG * W_IMG;
    const int pix = py * W_IMG + px;

    const int k = g_cnt[t];

    if (k == 0) {                              // empty tile fast path (g_cnt already 0)
        if (seg == 0) {
            out[3 * pix + 0] = bgr;
            out[3 * pix + 1] = bgg;
            out[3 * pix + 2] = bgb;
            float* o2 = out + 3 * HW + n;
            o2[pix] = 0.0f; o2[HW + pix] = 0.0f;
            o2[2 * HW + pix] = 0.0f; o2[3 * HW + pix] = 0.0f;
        }
        return;
    }

    // load keys for this tile
    for (int e = tid; e < k; e += 256) sKey[e] = g_list[t * MAXG + e];
    __syncthreads();
    if (tid == 0) g_cnt[t] = 0;                // reset for next launch/replay

    // stable z-rank via unique u64 keys; record LDGs overlap rank loop
    for (int e = tid; e < k; e += 256) {
        unsigned long long key = sKey[e];
        int ie = (int)(unsigned)(key & 0xffffffffu);
        float4 a = g_p1v[ie];
        float4 b = g_p2v[ie];
        float4 c = g_clv[ie];
        int r = 0;
        #pragma unroll 4
        for (int j = 0; j < k; j++) r += (sKey[j] < key) ? 1 : 0;
        sP1[r] = a; sP2[r] = b; sCl[r] = c;
    }
    if (tid < 3) {
        sP1[k + tid] = make_float4(0.f, 0.f, 0.f, 0.f);
        sP2[k + tid] = make_float4(0.f, 0.f, 0.f, -1.0f);  // pln<0 -> never kept
        sCl[k + tid] = make_float4(0.f, 0.f, 0.f, 0.f);
    }
    __syncthreads();

    // 4-way segmented compositing
    const float fpx = (float)px, fpy = (float)py;
    float T = 1.0f, aR = 0.f, aG = 0.f, aB = 0.f, dep = 0.f, mw = 0.f;
    int cnt = 0;
    const int q = (k + 3) >> 2;
    const int s0 = seg * q;
    #pragma unroll 2
    for (int j = 0; j < q; j++) {
        int idx = s0 + j;
        float4 p1 = sP1[idx];
        float4 p2 = sP2[idx];
        float dx = fpx - p1.x, dy = fpy - p1.y;
        float m = (p1.z * dx) * dx + (p2.x * dy) * dy + (p1.w * dx) * dy;
        bool kp = (m >= 0.0f) && (m <= p2.w);  // power<=0 && alpha>=1/255
        float al = fminf(0.99f, p2.y * __expf(-m));
        float a_eff = kp ? al : 0.0f;
        float4 c4 = sCl[idx];
        float wv = a_eff * T;
        aR = fmaf(wv, c4.x, aR);
        aG = fmaf(wv, c4.y, aG);
        aB = fmaf(wv, c4.z, aB);
        dep = fmaf(wv, p2.z, dep);
        mw = fmaxf(mw, wv);
        cnt += kp ? 1 : 0;
        T -= wv;
    }

    // merge 4 segment states (adjacent lanes)
    #pragma unroll
    for (int d = 1; d <= 2; d <<= 1) {
        float To = __shfl_xor_sync(0xffffffffu, T,  d);
        float ro = __shfl_xor_sync(0xffffffffu, aR, d);
        float go = __shfl_xor_sync(0xffffffffu, aG, d);
        float bo = __shfl_xor_sync(0xffffffffu, aB, d);
        float do_ = __shfl_xor_sync(0xffffffffu, dep, d);
        float mo = __shfl_xor_sync(0xffffffffu, mw, d);
        int   co = __shfl_xor_sync(0xffffffffu, cnt, d);
        bool rightSelf = (lane & d) != 0;
        float TL = rightSelf ? To : T,   TR = rightSelf ? T   : To;
        float rL = rightSelf ? ro : aR,  rR = rightSelf ? aR  : ro;
        float gL = rightSelf ? go : aG,  gR = rightSelf ? aG  : go;
        float bL = rightSelf ? bo : aB,  bR = rightSelf ? aB  : bo;
        float dL = rightSelf ? do_ : dep, dR = rightSelf ? dep : do_;
        float mL = rightSelf ? mo : mw,  mR = rightSelf ? mw  : mo;
        aR  = fmaf(TL, rR, rL);
        aG  = fmaf(TL, gR, gL);
        aB  = fmaf(TL, bR, bL);
        dep = fmaf(TL, dR, dL);
        mw  = fmaxf(mL, TL * mR);
        T   = TL * TR;
        cnt += co;
    }

    if (seg == 0) {
        out[3 * pix + 0] = aR + T * bgr;
        out[3 * pix + 1] = aG + T * bgg;
        out[3 * pix + 2] = aB + T * bgb;
        float* o2 = out + 3 * HW + n;
        o2[pix]          = (float)cnt;   // out_observe
        o2[HW + pix]     = dep;          // out_plane_depth
        o2[2 * HW + pix] = mw;           // app_opacity
        o2[3 * HW + pix] = 1.0f - T;     // color_alpha
    }
}

extern "C" void kernel_launch(void* const* d_in, const int* in_sizes, int n_in,
                              void* d_out, int out_size) {
    const float* means  = (const float*)d_in[0];
    const float* opac   = (const float*)d_in[1];
    const float* colors = (const float*)d_in[2];
    const float* scales = (const float*)d_in[3];
    const float* rots   = (const float*)d_in[4];
    const float* bg     = (const float*)d_in[5];
    const float* vm     = (const float*)d_in[6];
    const int n = in_sizes[0] / 3;
    float* out = (float*)d_out;

    gs_pre<<<(n + 63) / 64, 64>>>(means, opac, colors, scales, rots, vm,
                                  out + (size_t)3 * H_IMG * W_IMG, n);
    gs_raster<<<NTILES, 256>>>(bg, out, n);
}

// round 10
// speedup vs baseline: 9.0019x; 2.0636x over previous
#include <cuda_runtime.h>
#include <math.h>

#define H_IMG 256
#define W_IMG 256
#define TILE 8
#define NTX 32
#define NTILES 1024
#define TANFOV 0.7f
#define MAXG 512

__device__ float4 g_p1v[MAXG];               // mx, my, 0.5*conicA, conicB
__device__ float4 g_p2v[MAXG];               // 0.5*conicC, opacity, z, +ln(255*op)
__device__ float4 g_clv[MAXG];               // r, g, b, 0
__device__ int g_cnt[NTILES];                // ALWAYS zero at kernel_launch entry
__device__ unsigned long long g_list[NTILES * MAXG];

// One WARP per gaussian: redundant per-lane preprocess (no cross-lane deps),
// then 32 lanes cooperatively scatter the gaussian into its covered tiles.
__global__ __launch_bounds__(256) void gs_prebin(
    const float* __restrict__ means,
    const float* __restrict__ opac,
    const float* __restrict__ colors,
    const float* __restrict__ scales,
    const float* __restrict__ rots,
    const float* __restrict__ vm,
    float* __restrict__ radii_out, int n)
{
    const int i = (blockIdx.x * 256 + threadIdx.x) >> 5;   // gaussian id = global warp id
    const int lane = threadIdx.x & 31;
    if (i >= n) return;

    const float fx = W_IMG / (2.0f * TANFOV);
    const float fy = H_IMG / (2.0f * TANFOV);
    const float R00 = vm[0], R01 = vm[1], R02 = vm[2],  t0 = vm[3];
    const float R10 = vm[4], R11 = vm[5], R12 = vm[6],  t1 = vm[7];
    const float R20 = vm[8], R21 = vm[9], R22 = vm[10], t2 = vm[11];

    float m0 = means[3*i], m1 = means[3*i+1], m2 = means[3*i+2];
    float pxv = R00*m0 + R01*m1 + R02*m2 + t0;
    float pyv = R10*m0 + R11*m1 + R12*m2 + t1;
    float zg  = R20*m0 + R21*m1 + R22*m2 + t2;
    float zc = fmaxf(zg, 1e-4f);
    float lim = 1.3f * TANFOV;
    float txc = fminf(fmaxf(pxv/zc, -lim), lim) * zc;
    float tyc = fminf(fmaxf(pyv/zc, -lim), lim) * zc;

    float q0 = rots[4*i], q1 = rots[4*i+1], q2 = rots[4*i+2], q3 = rots[4*i+3];
    float qn = rsqrtf(q0*q0 + q1*q1 + q2*q2 + q3*q3);
    q0 *= qn; q1 *= qn; q2 *= qn; q3 *= qn;
    float xx = q1*q1, yy = q2*q2, zz = q3*q3;
    float xy = q1*q2, xz = q1*q3, yz = q2*q3;
    float rx = q0*q1, ry = q0*q2, rz = q0*q3;
    float Q00 = 1.f-2.f*(yy+zz), Q01 = 2.f*(xy-rz),     Q02 = 2.f*(xz+ry);
    float Q10 = 2.f*(xy+rz),     Q11 = 1.f-2.f*(xx+zz), Q12 = 2.f*(yz-rx);
    float Q20 = 2.f*(xz-ry),     Q21 = 2.f*(yz+rx),     Q22 = 1.f-2.f*(xx+yy);
    float sx = scales[3*i], sy = scales[3*i+1], sz2 = scales[3*i+2];
    float M00 = Q00*sx, M01 = Q01*sy, M02 = Q02*sz2;
    float M10 = Q10*sx, M11 = Q11*sy, M12 = Q12*sz2;
    float M20 = Q20*sx, M21 = Q21*sy, M22 = Q22*sz2;
    float C00 = M00*M00 + M01*M01 + M02*M02;
    float C01 = M00*M10 + M01*M11 + M02*M12;
    float C02 = M00*M20 + M01*M21 + M02*M22;
    float C11 = M10*M10 + M11*M11 + M12*M12;
    float C12 = M10*M20 + M11*M21 + M12*M22;
    float C22 = M20*M20 + M21*M21 + M22*M22;
    float j00 = fx/zc, j02 = -fx*txc/(zc*zc);
    float j11 = fy/zc, j12 = -fy*tyc/(zc*zc);
    float T00 = j00*R00 + j02*R20, T01 = j00*R01 + j02*R21, T02 = j00*R02 + j02*R22;
    float T10 = j11*R10 + j12*R20, T11 = j11*R11 + j12*R21, T12 = j11*R12 + j12*R22;
    float u0 = C00*T00 + C01*T01 + C02*T02;
    float u1 = C01*T00 + C11*T01 + C12*T02;
    float u2 = C02*T00 + C12*T01 + C22*T02;
    float v0 = C00*T10 + C01*T11 + C02*T12;
    float v1 = C01*T10 + C11*T11 + C12*T12;
    float v2 = C02*T10 + C12*T11 + C22*T12;
    float a  = T00*u0 + T01*u1 + T02*u2 + 0.3f;
    float bq = T10*u0 + T11*u1 + T12*u2;
    float c  = T10*v0 + T11*v1 + T12*v2 + 0.3f;
    float det = a*c - bq*bq;
    float inv_det = 1.0f / fmaxf(det, 1e-12f);
    float cA = c*inv_det, cB = -bq*inv_det, cC = a*inv_det;
    float mid = 0.5f*(a + c);
    float lam1 = mid + sqrtf(fmaxf(mid*mid - det, 0.1f));
    float mx = fx*pxv/zc + 0.5f*W_IMG - 0.5f;
    float my = fy*pyv/zc + 0.5f*H_IMG - 0.5f;
    bool valid = (zg > 0.2f) && (det > 0.0f);
    float op = opac[i];
    float pln = logf(255.0f * op);             // keep: 0 <= m <= pln

    if (lane == 0) {
        radii_out[i] = ceilf(3.0f * sqrtf(lam1));
        g_p1v[i] = make_float4(mx, my, 0.5f * cA, cB);
        g_p2v[i] = make_float4(0.5f * cC, op, zg, pln);
        g_clv[i] = make_float4(colors[3*i], colors[3*i+1], colors[3*i+2], 0.0f);
    }

    if (!(valid && pln > 0.0f)) return;
    float sthr = 2.0f * pln;
    float hx = sqrtf(sthr * a) * 1.001f + 0.6f;
    float hy = sqrtf(sthr * c) * 1.001f + 0.6f;
    if (!((mx + hx >= 0.f) && (mx - hx <= 255.f) &&
          (my + hy >= 0.f) && (my - hy <= 255.f))) return;

    int x0 = (int)fminf(fmaxf(floorf((mx - hx) * 0.125f), 0.f), 31.f);
    int x1 = (int)fminf(fmaxf(floorf((mx + hx) * 0.125f), 0.f), 31.f);
    int y0 = (int)fminf(fmaxf(floorf((my - hy) * 0.125f), 0.f), 31.f);
    int y1 = (int)fminf(fmaxf(floorf((my + hy) * 0.125f), 0.f), 31.f);
    int w = x1 - x0 + 1;
    int cnt = w * (y1 - y0 + 1);
    unsigned long long key =
        ((unsigned long long)__float_as_uint(zg) << 32) | (unsigned)i;

    // 32 lanes × 4-way unrolled scatter (independent atomics -> MLP 4)
    for (int jb = lane; jb < cnt; jb += 128) {
        #pragma unroll
        for (int u = 0; u < 4; u++) {
            int j = jb + u * 32;
            if (j < cnt) {
                int ty = y0 + j / w;
                int tx = x0 + j % w;
                int t = ty * NTX + tx;
                int pos = atomicAdd(&g_cnt[t], 1);
                g_list[t * MAXG + pos] = key;
            }
        }
    }
}

__global__ __launch_bounds__(128) void gs_raster(
    const float* __restrict__ bg, float* __restrict__ out, int n)
{
    __shared__ float4 sP1[MAXG + 4];
    __shared__ float4 sP2[MAXG + 4];
    __shared__ float4 sCl[MAXG + 4];
    __shared__ unsigned long long sKey[MAXG];

    const int tid  = threadIdx.x;
    const int lane = tid & 31;
    const int seg = tid & 3;
    const int pp  = tid >> 2;                  // pixel pair 0..31
    const int p0  = pp * 2;                    // even pixel of the pair
    const int bx = blockIdx.x & (NTX - 1), by = blockIdx.x >> 5;
    const int t  = blockIdx.x;
    const int px = bx * TILE + (p0 & (TILE - 1));
    const int py = by * TILE + (p0 >> 3);
    const float bgr = bg[0], bgg = bg[1], bgb = bg[2];
    const int HW = H_IMG * W_IMG;
    const int pix = py * W_IMG + px;           // even pixel; odd is pix+1

    const int k = g_cnt[t];

    if (k == 0) {                              // empty tile fast path
        if (seg == 0) {
            float* o2 = out + 3 * HW + n;
            #pragma unroll
            for (int u = 0; u < 2; u++) {
                int px_ = pix + u;
                out[3 * px_ + 0] = bgr;
                out[3 * px_ + 1] = bgg;
                out[3 * px_ + 2] = bgb;
                o2[px_] = 0.0f; o2[HW + px_] = 0.0f;
                o2[2 * HW + px_] = 0.0f; o2[3 * HW + px_] = 0.0f;
            }
        }
        return;
    }

    // load keys for this tile
    for (int e = tid; e < k; e += 128) sKey[e] = g_list[t * MAXG + e];
    __syncthreads();
    if (tid == 0) g_cnt[t] = 0;                // reset for next launch/replay

    // stable z-rank via unique u64 keys; record LDGs overlap rank loop
    for (int e = tid; e < k; e += 128) {
        unsigned long long key = sKey[e];
        int ie = (int)(unsigned)(key & 0xffffffffu);
        float4 a = g_p1v[ie];
        float4 b = g_p2v[ie];
        float4 c = g_clv[ie];
        int r = 0;
        #pragma unroll 4
        for (int j = 0; j < k; j++) r += (sKey[j] < key) ? 1 : 0;
        sP1[r] = a; sP2[r] = b; sCl[r] = c;
    }
    if (tid < 3) {
        sP1[k + tid] = make_float4(0.f, 0.f, 0.f, 0.f);
        sP2[k + tid] = make_float4(0.f, 0.f, 0.f, -1.0f);  // pln<0 -> never kept
        sCl[k + tid] = make_float4(0.f, 0.f, 0.f, 0.f);
    }
    __syncthreads();

    // 4-way segmented compositing, 2 pixels per thread
    const float fpx = (float)px, fpy = (float)py;
    float T0 = 1.0f, aR0 = 0.f, aG0 = 0.f, aB0 = 0.f, dep0 = 0.f, mw0 = 0.f;
    float T1 = 1.0f, aR1 = 0.f, aG1 = 0.f, aB1 = 0.f, dep1 = 0.f, mw1 = 0.f;
    int cnt0 = 0, cnt1 = 0;
    const int q = (k + 3) >> 2;
    const int s0 = seg * q;
    #pragma unroll 2
    for (int j = 0; j < q; j++) {
        int idx = s0 + j;
        float4 p1 = sP1[idx];
        float4 p2 = sP2[idx];
        float4 c4 = sCl[idx];
        float dy = fpy - p1.y;
        float tyy = (p2.x * dy) * dy;          // shared 0.5*cC*dy^2 term
        float dx0 = fpx - p1.x;
        float dx1 = dx0 + 1.0f;
        float m0 = (p1.z * dx0) * dx0 + tyy + (p1.w * dx0) * dy;
        float m1 = (p1.z * dx1) * dx1 + tyy + (p1.w * dx1) * dy;
        bool kp0 = (m0 >= 0.0f) && (m0 <= p2.w);
        bool kp1 = (m1 >= 0.0f) && (m1 <= p2.w);
        float al0 = fminf(0.99f, p2.y * __expf(-m0));
        float al1 = fminf(0.99f, p2.y * __expf(-m1));
        float ae0 = kp0 ? al0 : 0.0f;
        float ae1 = kp1 ? al1 : 0.0f;
        float wv0 = ae0 * T0;
        float wv1 = ae1 * T1;
        aR0 = fmaf(wv0, c4.x, aR0); aR1 = fmaf(wv1, c4.x, aR1);
        aG0 = fmaf(wv0, c4.y, aG0); aG1 = fmaf(wv1, c4.y, aG1);
        aB0 = fmaf(wv0, c4.z, aB0); aB1 = fmaf(wv1, c4.z, aB1);
        dep0 = fmaf(wv0, p2.z, dep0); dep1 = fmaf(wv1, p2.z, dep1);
        mw0 = fmaxf(mw0, wv0); mw1 = fmaxf(mw1, wv1);
        cnt0 += kp0 ? 1 : 0; cnt1 += kp1 ? 1 : 0;
        T0 -= wv0; T1 -= wv1;
    }

    // merge 4 segment states per pixel (adjacent lanes)
    #pragma unroll
    for (int d = 1; d <= 2; d <<= 1) {
        bool rs = (lane & d) != 0;
        #pragma unroll
        for (int u = 0; u < 2; u++) {
            float &T = u ? T1 : T0;
            float &aR = u ? aR1 : aR0, &aG = u ? aG1 : aG0, &aB = u ? aB1 : aB0;
            float &dep = u ? dep1 : dep0, &mw = u ? mw1 : mw0;
            int &cnt = u ? cnt1 : cnt0;
            float To = __shfl_xor_sync(0xffffffffu, T,  d);
            float ro = __shfl_xor_sync(0xffffffffu, aR, d);
            float go = __shfl_xor_sync(0xffffffffu, aG, d);
            float bo = __shfl_xor_sync(0xffffffffu, aB, d);
            float do_ = __shfl_xor_sync(0xffffffffu, dep, d);
            float mo = __shfl_xor_sync(0xffffffffu, mw, d);
            int   co = __shfl_xor_sync(0xffffffffu, cnt, d);
            float TL = rs ? To : T,   TR = rs ? T   : To;
            float rL = rs ? ro : aR,  rR = rs ? aR  : ro;
            float gL = rs ? go : aG,  gR = rs ? aG  : go;
            float bL = rs ? bo : aB,  bR = rs ? aB  : bo;
            float dL = rs ? do_ : dep, dR = rs ? dep : do_;
            float mL = rs ? mo : mw,  mR = rs ? mw  : mo;
            aR  = fmaf(TL, rR, rL);
            aG  = fmaf(TL, gR, gL);
            aB  = fmaf(TL, bR, bL);
            dep = fmaf(TL, dR, dL);
            mw  = fmaxf(mL, TL * mR);
            T   = TL * TR;
            cnt += co;
        }
    }

    if (seg == 0) {
        float* o2 = out + 3 * HW + n;
        out[3 * pix + 0] = aR0 + T0 * bgr;
        out[3 * pix + 1] = aG0 + T0 * bgg;
        out[3 * pix + 2] = aB0 + T0 * bgb;
        o2[pix]          = (float)cnt0;
        o2[HW + pix]     = dep0;
        o2[2 * HW + pix] = mw0;
        o2[3 * HW + pix] = 1.0f - T0;
        int pix1 = pix + 1;
        out[3 * pix1 + 0] = aR1 + T1 * bgr;
        out[3 * pix1 + 1] = aG1 + T1 * bgg;
        out[3 * pix1 + 2] = aB1 + T1 * bgb;
        o2[pix1]          = (float)cnt1;
        o2[HW + pix1]     = dep1;
        o2[2 * HW + pix1] = mw1;
        o2[3 * HW + pix1] = 1.0f - T1;
    }
}

extern "C" void kernel_launch(void* const* d_in, const int* in_sizes, int n_in,
                              void* d_out, int out_size) {
    const float* means  = (const float*)d_in[0];
    const float* opac   = (const float*)d_in[1];
    const float* colors = (const float*)d_in[2];
    const float* scales = (const float*)d_in[3];
    const float* rots   = (const float*)d_in[4];
    const float* bg     = (const float*)d_in[5];
    const float* vm     = (const float*)d_in[6];
    const int n = in_sizes[0] / 3;
    float* out = (float*)d_out;

    int nwarps_blocks = (n * 32 + 255) / 256;
    gs_prebin<<<nwarps_blocks, 256>>>(means, opac, colors, scales, rots, vm,
                                      out + (size_t)3 * H_IMG * W_IMG, n);
    gs_raster<<<NTILES, 128>>>(bg, out, n);
}

// round 11
// speedup vs baseline: 10.4017x; 1.1555x over previous
#include <cuda_runtime.h>
#include <math.h>

#define H_IMG 256
#define W_IMG 256
#define TILE 16
#define NTX 16
#define NTILES 256
#define TANFOV 0.7f
#define MAXG 512

__device__ float4 g_p1v[MAXG];               // mx, my, 0.5*conicA, conicB
__device__ float4 g_p2v[MAXG];               // 0.5*conicC, opacity, z, +ln(255*op)
__device__ float4 g_clv[MAXG];               // r, g, b, 0
__device__ int g_cnt[NTILES];                // ALWAYS zero at kernel_launch entry
__device__ unsigned long long g_list[NTILES * MAXG];

// One WARP per gaussian: redundant per-lane preprocess, then the 32 lanes
// cooperatively scatter the gaussian into its covered 16x16 tiles.
__global__ __launch_bounds__(256) void gs_prebin(
    const float* __restrict__ means,
    const float* __restrict__ opac,
    const float* __restrict__ colors,
    const float* __restrict__ scales,
    const float* __restrict__ rots,
    const float* __restrict__ vm,
    float* __restrict__ radii_out, int n)
{
    const int i = (blockIdx.x * 256 + threadIdx.x) >> 5;   // gaussian id = warp id
    const int lane = threadIdx.x & 31;
    if (i >= n) return;

    const float fx = W_IMG / (2.0f * TANFOV);
    const float fy = H_IMG / (2.0f * TANFOV);
    const float R00 = vm[0], R01 = vm[1], R02 = vm[2],  t0 = vm[3];
    const float R10 = vm[4], R11 = vm[5], R12 = vm[6],  t1 = vm[7];
    const float R20 = vm[8], R21 = vm[9], R22 = vm[10], t2 = vm[11];

    float m0 = means[3*i], m1 = means[3*i+1], m2 = means[3*i+2];
    float pxv = R00*m0 + R01*m1 + R02*m2 + t0;
    float pyv = R10*m0 + R11*m1 + R12*m2 + t1;
    float zg  = R20*m0 + R21*m1 + R22*m2 + t2;
    float zc = fmaxf(zg, 1e-4f);
    float lim = 1.3f * TANFOV;
    float txc = fminf(fmaxf(pxv/zc, -lim), lim) * zc;
    float tyc = fminf(fmaxf(pyv/zc, -lim), lim) * zc;

    float q0 = rots[4*i], q1 = rots[4*i+1], q2 = rots[4*i+2], q3 = rots[4*i+3];
    float qn = rsqrtf(q0*q0 + q1*q1 + q2*q2 + q3*q3);
    q0 *= qn; q1 *= qn; q2 *= qn; q3 *= qn;
    float xx = q1*q1, yy = q2*q2, zz = q3*q3;
    float xy = q1*q2, xz = q1*q3, yz = q2*q3;
    float rx = q0*q1, ry = q0*q2, rz = q0*q3;
    float Q00 = 1.f-2.f*(yy+zz), Q01 = 2.f*(xy-rz),     Q02 = 2.f*(xz+ry);
    float Q10 = 2.f*(xy+rz),     Q11 = 1.f-2.f*(xx+zz), Q12 = 2.f*(yz-rx);
    float Q20 = 2.f*(xz-ry),     Q21 = 2.f*(yz+rx),     Q22 = 1.f-2.f*(xx+yy);
    float sx = scales[3*i], sy = scales[3*i+1], sz2 = scales[3*i+2];
    float M00 = Q00*sx, M01 = Q01*sy, M02 = Q02*sz2;
    float M10 = Q10*sx, M11 = Q11*sy, M12 = Q12*sz2;
    float M20 = Q20*sx, M21 = Q21*sy, M22 = Q22*sz2;
    float C00 = M00*M00 + M01*M01 + M02*M02;
    float C01 = M00*M10 + M01*M11 + M02*M12;
    float C02 = M00*M20 + M01*M21 + M02*M22;
    float C11 = M10*M10 + M11*M11 + M12*M12;
    float C12 = M10*M20 + M11*M21 + M12*M22;
    float C22 = M20*M20 + M21*M21 + M22*M22;
    float j00 = fx/zc, j02 = -fx*txc/(zc*zc);
    float j11 = fy/zc, j12 = -fy*tyc/(zc*zc);
    float T00 = j00*R00 + j02*R20, T01 = j00*R01 + j02*R21, T02 = j00*R02 + j02*R22;
    float T10 = j11*R10 + j12*R20, T11 = j11*R11 + j12*R21, T12 = j11*R12 + j12*R22;
    float u0 = C00*T00 + C01*T01 + C02*T02;
    float u1 = C01*T00 + C11*T01 + C12*T02;
    float u2 = C02*T00 + C12*T01 + C22*T02;
    float v0 = C00*T10 + C01*T11 + C02*T12;
    float v1 = C01*T10 + C11*T11 + C12*T12;
    float v2 = C02*T10 + C12*T11 + C22*T12;
    float a  = T00*u0 + T01*u1 + T02*u2 + 0.3f;
    float bq = T10*u0 + T11*u1 + T12*u2;
    float c  = T10*v0 + T11*v1 + T12*v2 + 0.3f;
    float det = a*c - bq*bq;
    float inv_det = 1.0f / fmaxf(det, 1e-12f);
    float cA = c*inv_det, cB = -bq*inv_det, cC = a*inv_det;
    float mid = 0.5f*(a + c);
    float lam1 = mid + sqrtf(fmaxf(mid*mid - det, 0.1f));
    float mx = fx*pxv/zc + 0.5f*W_IMG - 0.5f;
    float my = fy*pyv/zc + 0.5f*H_IMG - 0.5f;
    bool valid = (zg > 0.2f) && (det > 0.0f);
    float op = opac[i];
    float pln = logf(255.0f * op);             // keep: 0 <= m <= pln

    if (lane == 0) {
        radii_out[i] = ceilf(3.0f * sqrtf(lam1));
        g_p1v[i] = make_float4(mx, my, 0.5f * cA, cB);
        g_p2v[i] = make_float4(0.5f * cC, op, zg, pln);
        g_clv[i] = make_float4(colors[3*i], colors[3*i+1], colors[3*i+2], 0.0f);
    }

    if (!(valid && pln > 0.0f)) return;
    float sthr = 2.0f * pln;
    float hx = sqrtf(sthr * a) * 1.001f + 0.6f;
    float hy = sqrtf(sthr * c) * 1.001f + 0.6f;
    if (!((mx + hx >= 0.f) && (mx - hx <= 255.f) &&
          (my + hy >= 0.f) && (my - hy <= 255.f))) return;

    const float inv_t = 1.0f / (float)TILE;
    int x0 = (int)fminf(fmaxf(floorf((mx - hx) * inv_t), 0.f), (float)(NTX - 1));
    int x1 = (int)fminf(fmaxf(floorf((mx + hx) * inv_t), 0.f), (float)(NTX - 1));
    int y0 = (int)fminf(fmaxf(floorf((my - hy) * inv_t), 0.f), (float)(NTX - 1));
    int y1 = (int)fminf(fmaxf(floorf((my + hy) * inv_t), 0.f), (float)(NTX - 1));
    int w = x1 - x0 + 1;
    int cnt = w * (y1 - y0 + 1);
    unsigned long long key =
        ((unsigned long long)__float_as_uint(zg) << 32) | (unsigned)i;

    // 32 lanes × 4-way unrolled scatter (independent atomics -> MLP 4)
    for (int jb = lane; jb < cnt; jb += 128) {
        #pragma unroll
        for (int u = 0; u < 4; u++) {
            int j = jb + u * 32;
            if (j < cnt) {
                int ty = y0 + j / w;
                int tx = x0 + j % w;
                int t = ty * NTX + tx;
                int pos = atomicAdd(&g_cnt[t], 1);
                g_list[t * MAXG + pos] = key;
            }
        }
    }
}

__global__ __launch_bounds__(512) void gs_raster(
    const float* __restrict__ bg, float* __restrict__ out, int n)
{
    __shared__ float4 sP1[MAXG + 2];
    __shared__ float4 sP2[MAXG + 2];
    __shared__ float4 sCl[MAXG + 2];
    __shared__ unsigned long long sKey[MAXG];

    const int tid  = threadIdx.x;
    const int lane = tid & 31;
    const int seg = tid & 1;                   // 2 segments per pixel
    const int p   = tid >> 1;                  // pixel 0..255 within tile
    const int bx = blockIdx.x & (NTX - 1), by = blockIdx.x >> 4;
    const int t  = blockIdx.x;
    const int px = bx * TILE + (p & (TILE - 1));
    const int py = by * TILE + (p >> 4);
    const float bgr = bg[0], bgg = bg[1], bgb = bg[2];
    const int HW = H_IMG * W_IMG;
    const int pix = py * W_IMG + px;

    const int k = g_cnt[t];

    if (k == 0) {                              // empty tile fast path
        if (seg == 0) {
            float* o2 = out + 3 * HW + n;
            out[3 * pix + 0] = bgr;
            out[3 * pix + 1] = bgg;
            out[3 * pix + 2] = bgb;
            o2[pix] = 0.0f; o2[HW + pix] = 0.0f;
            o2[2 * HW + pix] = 0.0f; o2[3 * HW + pix] = 0.0f;
        }
        return;
    }

    // load keys for this tile
    for (int e = tid; e < k; e += 512) sKey[e] = g_list[t * MAXG + e];
    __syncthreads();
    if (tid == 0) g_cnt[t] = 0;                // reset for next launch/replay

    // stable z-rank via unique u64 keys; record LDGs overlap rank loop
    if (tid < k) {
        unsigned long long key = sKey[tid];
        int ie = (int)(unsigned)(key & 0xffffffffu);
        float4 a = g_p1v[ie];
        float4 b = g_p2v[ie];
        float4 c = g_clv[ie];
        int r = 0;
        #pragma unroll 4
        for (int j = 0; j < k; j++) r += (sKey[j] < key) ? 1 : 0;
        sP1[r] = a; sP2[r] = b; sCl[r] = c;
    }
    if (tid < 2) {
        sP1[k + tid] = make_float4(0.f, 0.f, 0.f, 0.f);
        sP2[k + tid] = make_float4(0.f, 0.f, 0.f, -1.0f);  // pln<0 -> never kept
        sCl[k + tid] = make_float4(0.f, 0.f, 0.f, 0.f);
    }
    __syncthreads();

    // 2-way segmented compositing
    const float fpx = (float)px, fpy = (float)py;
    float T = 1.0f, aR = 0.f, aG = 0.f, aB = 0.f, dep = 0.f, mw = 0.f;
    int cnt = 0;
    const int q = (k + 1) >> 1;
    const int s0 = seg * q;
    #pragma unroll 2
    for (int j = 0; j < q; j++) {
        int idx = s0 + j;
        float4 p1 = sP1[idx];
        float4 p2 = sP2[idx];
        float dx = fpx - p1.x, dy = fpy - p1.y;
        float m = (p1.z * dx) * dx + (p2.x * dy) * dy + (p1.w * dx) * dy;
        bool kp = (m >= 0.0f) && (m <= p2.w);  // power<=0 && alpha>=1/255
        float al = fminf(0.99f, p2.y * __expf(-m));
        float a_eff = kp ? al : 0.0f;
        float4 c4 = sCl[idx];
        float wv = a_eff * T;
        aR = fmaf(wv, c4.x, aR);
        aG = fmaf(wv, c4.y, aG);
        aB = fmaf(wv, c4.z, aB);
        dep = fmaf(wv, p2.z, dep);
        mw = fmaxf(mw, wv);
        cnt += kp ? 1 : 0;
        T -= wv;
    }

    // merge the 2 segment states (adjacent lanes)
    {
        const int d = 1;
        bool rs = (lane & d) != 0;
        float To = __shfl_xor_sync(0xffffffffu, T,  d);
        float ro = __shfl_xor_sync(0xffffffffu, aR, d);
        float go = __shfl_xor_sync(0xffffffffu, aG, d);
        float bo = __shfl_xor_sync(0xffffffffu, aB, d);
        float do_ = __shfl_xor_sync(0xffffffffu, dep, d);
        float mo = __shfl_xor_sync(0xffffffffu, mw, d);
        int   co = __shfl_xor_sync(0xffffffffu, cnt, d);
        float TL = rs ? To : T,   TR = rs ? T   : To;
        float rL = rs ? ro : aR,  rR = rs ? aR  : ro;
        float gL = rs ? go : aG,  gR = rs ? aG  : go;
        float bL = rs ? bo : aB,  bR = rs ? aB  : bo;
        float dL = rs ? do_ : dep, dR = rs ? dep : do_;
        float mL = rs ? mo : mw,  mR = rs ? mw  : mo;
        aR  = fmaf(TL, rR, rL);
        aG  = fmaf(TL, gR, gL);
        aB  = fmaf(TL, bR, bL);
        dep = fmaf(TL, dR, dL);
        mw  = fmaxf(mL, TL * mR);
        T   = TL * TR;
        cnt += co;
    }

    if (seg == 0) {
        float* o2 = out + 3 * HW + n;
        out[3 * pix + 0] = aR + T * bgr;
        out[3 * pix + 1] = aG + T * bgg;
        out[3 * pix + 2] = aB + T * bgb;
        o2[pix]          = (float)cnt;   // out_observe
        o2[HW + pix]     = dep;          // out_plane_depth
        o2[2 * HW + pix] = mw;           // app_opacity
        o2[3 * HW + pix] = 1.0f - T;     // color_alpha
    }
}

extern "C" void kernel_launch(void* const* d_in, const int* in_sizes, int n_in,
                              void* d_out, int out_size) {
    const float* means  = (const float*)d_in[0];
    const float* opac   = (const float*)d_in[1];
    const float* colors = (const float*)d_in[2];
    const float* scales = (const float*)d_in[3];
    const float* rots   = (const float*)d_in[4];
    const float* bg     = (const float*)d_in[5];
    const float* vm     = (const float*)d_in[6];
    const int n = in_sizes[0] / 3;
    float* out = (float*)d_out;

    int prebin_blocks = (n * 32 + 255) / 256;
    gs_prebin<<<prebin_blocks, 256>>>(means, opac, colors, scales, rots, vm,
                                      out + (size_t)3 * H_IMG * W_IMG, n);
    gs_raster<<<NTILES, 512>>>(bg, out, n);
}

// round 12
// speedup vs baseline: 12.0400x; 1.1575x over previous
#include <cuda_runtime.h>
#include <math.h>

#define H_IMG 256
#define W_IMG 256
#define TILE 16
#define NTX 16
#define NTILES 256
#define TANFOV 0.7f
#define MAXG 512

__global__ __launch_bounds__(512) void gs_fused(
    const float* __restrict__ means,
    const float* __restrict__ opac,
    const float* __restrict__ colors,
    const float* __restrict__ scales,
    const float* __restrict__ rots,
    const float* __restrict__ bg,
    const float* __restrict__ vm,
    float* __restrict__ out, int n)
{
    __shared__ float4 sP1[MAXG + 2];   // mx, my, 0.5*cA, cB
    __shared__ float4 sP2[MAXG + 2];   // 0.5*cC, op, z, pln
    __shared__ float4 sCl[MAXG + 2];   // r, g, b, 0
    __shared__ unsigned long long sKey[MAXG];
    __shared__ int sK;

    const int tid  = threadIdx.x;
    const int lane = tid & 31;
    const int bx = blockIdx.x & (NTX - 1), by = blockIdx.x >> 4;
    const float tX0 = (float)(bx * TILE), tX1 = tX0 + (TILE - 1);
    const float tY0 = (float)(by * TILE), tY1 = tY0 + (TILE - 1);

    const float fx = W_IMG / (2.0f * TANFOV);
    const float fy = H_IMG / (2.0f * TANFOV);
    const float R00 = vm[0], R01 = vm[1], R02 = vm[2],  t0 = vm[3];
    const float R10 = vm[4], R11 = vm[5], R12 = vm[6],  t1 = vm[7];
    const float R20 = vm[8], R21 = vm[9], R22 = vm[10], t2 = vm[11];
    const float bgr = bg[0], bgg = bg[1], bgb = bg[2];
    float* radii_out = out + (size_t)3 * H_IMG * W_IMG;

    if (tid == 0) sK = 0;
    __syncthreads();

    // ---- Phase A: one gaussian per thread, preprocess + cull + compaction ----
    bool pred = false;
    float4 p1v, p2v, clv;
    unsigned long long key = 0ull;
    if (tid < n) {
        const int i = tid;
        float m0 = means[3*i], m1 = means[3*i+1], m2 = means[3*i+2];
        float pxv = R00*m0 + R01*m1 + R02*m2 + t0;
        float pyv = R10*m0 + R11*m1 + R12*m2 + t1;
        float zg  = R20*m0 + R21*m1 + R22*m2 + t2;
        float zc = fmaxf(zg, 1e-4f);
        float lim = 1.3f * TANFOV;
        float txc = fminf(fmaxf(pxv/zc, -lim), lim) * zc;
        float tyc = fminf(fmaxf(pyv/zc, -lim), lim) * zc;

        float q0 = rots[4*i], q1 = rots[4*i+1], q2 = rots[4*i+2], q3 = rots[4*i+3];
        float qn = rsqrtf(q0*q0 + q1*q1 + q2*q2 + q3*q3);
        q0 *= qn; q1 *= qn; q2 *= qn; q3 *= qn;
        float xx = q1*q1, yy = q2*q2, zz = q3*q3;
        float xy = q1*q2, xz = q1*q3, yz = q2*q3;
        float rx = q0*q1, ry = q0*q2, rz = q0*q3;
        float Q00 = 1.f-2.f*(yy+zz), Q01 = 2.f*(xy-rz),     Q02 = 2.f*(xz+ry);
        float Q10 = 2.f*(xy+rz),     Q11 = 1.f-2.f*(xx+zz), Q12 = 2.f*(yz-rx);
        float Q20 = 2.f*(xz-ry),     Q21 = 2.f*(yz+rx),     Q22 = 1.f-2.f*(xx+yy);
        float sx = scales[3*i], sy = scales[3*i+1], sz2 = scales[3*i+2];
        float M00 = Q00*sx, M01 = Q01*sy, M02 = Q02*sz2;
        float M10 = Q10*sx, M11 = Q11*sy, M12 = Q12*sz2;
        float M20 = Q20*sx, M21 = Q21*sy, M22 = Q22*sz2;
        float C00 = M00*M00 + M01*M01 + M02*M02;
        float C01 = M00*M10 + M01*M11 + M02*M12;
        float C02 = M00*M20 + M01*M21 + M02*M22;
        float C11 = M10*M10 + M11*M11 + M12*M12;
        float C12 = M10*M20 + M11*M21 + M12*M22;
        float C22 = M20*M20 + M21*M21 + M22*M22;
        float j00 = fx/zc, j02 = -fx*txc/(zc*zc);
        float j11 = fy/zc, j12 = -fy*tyc/(zc*zc);
        float T00 = j00*R00 + j02*R20, T01 = j00*R01 + j02*R21, T02 = j00*R02 + j02*R22;
        float T10 = j11*R10 + j12*R20, T11 = j11*R11 + j12*R21, T12 = j11*R12 + j12*R22;
        float u0 = C00*T00 + C01*T01 + C02*T02;
        float u1 = C01*T00 + C11*T01 + C12*T02;
        float u2 = C02*T00 + C12*T01 + C22*T02;
        float v0 = C00*T10 + C01*T11 + C02*T12;
        float v1 = C01*T10 + C11*T11 + C12*T12;
        float v2 = C02*T10 + C12*T11 + C22*T12;
        float a  = T00*u0 + T01*u1 + T02*u2 + 0.3f;
        float bq = T10*u0 + T11*u1 + T12*u2;
        float c  = T10*v0 + T11*v1 + T12*v2 + 0.3f;
        float det = a*c - bq*bq;
        float inv_det = 1.0f / fmaxf(det, 1e-12f);
        float cA = c*inv_det, cB = -bq*inv_det, cC = a*inv_det;
        float mid = 0.5f*(a + c);
        float lam1 = mid + sqrtf(fmaxf(mid*mid - det, 0.1f));
        if (bx == 0 && by == 0)
            radii_out[i] = ceilf(3.0f * sqrtf(lam1));
        float mx = fx*pxv/zc + 0.5f*W_IMG - 0.5f;
        float my = fy*pyv/zc + 0.5f*H_IMG - 0.5f;
        bool valid = (zg > 0.2f) && (det > 0.0f);
        float op = opac[i];
        float pln = logf(255.0f * op);            // keep: 0 <= m <= pln
        if (valid && pln > 0.0f) {
            float sthr = 2.0f * pln;
            float hx = sqrtf(sthr * a) * 1.001f + 0.6f;
            float hy = sqrtf(sthr * c) * 1.001f + 0.6f;
            pred = (mx - hx <= tX1) && (mx + hx >= tX0) &&
                   (my - hy <= tY1) && (my + hy >= tY0);
        }
        p1v = make_float4(mx, my, 0.5f * cA, cB);
        p2v = make_float4(0.5f * cC, op, zg, pln);
        clv = make_float4(colors[3*i], colors[3*i+1], colors[3*i+2], 0.0f);
        key = ((unsigned long long)__float_as_uint(zg) << 32) | (unsigned)i;
    }
    unsigned msk = __ballot_sync(0xffffffffu, pred);
    int nset = __popc(msk);
    int base_s = 0;
    if (lane == 0 && nset) base_s = atomicAdd(&sK, nset);
    base_s = __shfl_sync(0xffffffffu, base_s, 0);
    if (pred) {
        int slot = base_s + __popc(msk & ((1u << lane) - 1u));
        sKey[slot] = key;
        sP1[slot] = p1v; sP2[slot] = p2v; sCl[slot] = clv;
    }
    __syncthreads();

    const int k = sK;
    const int seg = tid & 1;
    const int p   = tid >> 1;                   // pixel 0..255
    const int px  = bx * TILE + (p & (TILE - 1));
    const int py  = by * TILE + (p >> 4);
    const int HW  = H_IMG * W_IMG;
    const int pix = py * W_IMG + px;

    if (k == 0) {
        if (seg == 0) {
            float* o2 = out + 3 * HW + n;
            out[3 * pix + 0] = bgr;
            out[3 * pix + 1] = bgg;
            out[3 * pix + 2] = bgb;
            o2[pix] = 0.0f; o2[HW + pix] = 0.0f;
            o2[2 * HW + pix] = 0.0f; o2[3 * HW + pix] = 0.0f;
        }
        return;
    }

    // ---- Phase B: register-carried stable z-rank permute ----
    float4 r1, r2, rc;
    unsigned long long mykey = 0ull;
    int r = 0;
    const bool hv = (tid < k);
    if (hv) {
        mykey = sKey[tid];
        r1 = sP1[tid]; r2 = sP2[tid]; rc = sCl[tid];
    }
    if (tid < ((k + 31) & ~31)) {               // whole warps beyond k skip
        #pragma unroll 4
        for (int j = 0; j < k; j++) r += (sKey[j] < mykey) ? 1 : 0;
    }
    __syncthreads();
    if (hv) { sP1[r] = r1; sP2[r] = r2; sCl[r] = rc; }
    if (tid < 2) {
        sP1[k + tid] = make_float4(0.f, 0.f, 0.f, 0.f);
        sP2[k + tid] = make_float4(0.f, 0.f, 0.f, -1.0f);   // pln<0 -> never kept
        sCl[k + tid] = make_float4(0.f, 0.f, 0.f, 0.f);
    }
    __syncthreads();

    // ---- Phase C: 2-way segmented compositing ----
    const float fpx = (float)px, fpy = (float)py;
    float T = 1.0f, aR = 0.f, aG = 0.f, aB = 0.f, dep = 0.f, mw = 0.f;
    int cnt = 0;
    const int q = (k + 1) >> 1;
    const int s0 = seg * q;
    #pragma unroll 2
    for (int j = 0; j < q; j++) {
        int idx = s0 + j;
        float4 p1 = sP1[idx];
        float4 p2 = sP2[idx];
        float dx = fpx - p1.x, dy = fpy - p1.y;
        float m = (p1.z * dx) * dx + (p2.x * dy) * dy + (p1.w * dx) * dy;
        bool kp = (m >= 0.0f) && (m <= p2.w);   // power<=0 && alpha>=1/255
        float al = fminf(0.99f, p2.y * __expf(-m));
        float a_eff = kp ? al : 0.0f;
        float4 c4 = sCl[idx];
        float wv = a_eff * T;
        aR = fmaf(wv, c4.x, aR);
        aG = fmaf(wv, c4.y, aG);
        aB = fmaf(wv, c4.z, aB);
        dep = fmaf(wv, p2.z, dep);
        mw = fmaxf(mw, wv);
        cnt += kp ? 1 : 0;
        T -= wv;
    }

    // merge the 2 segment states (adjacent lanes)
    {
        bool rs = (lane & 1) != 0;
        float To = __shfl_xor_sync(0xffffffffu, T,  1);
        float ro = __shfl_xor_sync(0xffffffffu, aR, 1);
        float go = __shfl_xor_sync(0xffffffffu, aG, 1);
        float bo = __shfl_xor_sync(0xffffffffu, aB, 1);
        float do_ = __shfl_xor_sync(0xffffffffu, dep, 1);
        float mo = __shfl_xor_sync(0xffffffffu, mw, 1);
        int   co = __shfl_xor_sync(0xffffffffu, cnt, 1);
        float TL = rs ? To : T,   TR = rs ? T   : To;
        float rL = rs ? ro : aR,  rR = rs ? aR  : ro;
        float gL = rs ? go : aG,  gR = rs ? aG  : go;
        float bL = rs ? bo : aB,  bR = rs ? aB  : bo;
        float dL = rs ? do_ : dep, dR = rs ? dep : do_;
        float mL = rs ? mo : mw,  mR = rs ? mw  : mo;
        aR  = fmaf(TL, rR, rL);
        aG  = fmaf(TL, gR, gL);
        aB  = fmaf(TL, bR, bL);
        dep = fmaf(TL, dR, dL);
        mw  = fmaxf(mL, TL * mR);
        T   = TL * TR;
        cnt += co;
    }

    if (seg == 0) {
        float* o2 = out + 3 * HW + n;
        out[3 * pix + 0] = aR + T * bgr;
        out[3 * pix + 1] = aG + T * bgg;
        out[3 * pix + 2] = aB + T * bgb;
        o2[pix]          = (float)cnt;   // out_observe
        o2[HW + pix]     = dep;          // out_plane_depth
        o2[2 * HW + pix] = mw;           // app_opacity
        o2[3 * HW + pix] = 1.0f - T;     // color_alpha
    }
}

extern "C" void kernel_launch(void* const* d_in, const int* in_sizes, int n_in,
                              void* d_out, int out_size) {
    const float* means  = (const float*)d_in[0];
    const float* opac   = (const float*)d_in[1];
    const float* colors = (const float*)d_in[2];
    const float* scales = (const float*)d_in[3];
    const float* rots   = (const float*)d_in[4];
    const float* bg     = (const float*)d_in[5];
    const float* vm     = (const float*)d_in[6];
    const int n = in_sizes[0] / 3;
    float* out = (float*)d_out;

    gs_fused<<<NTILES, 512>>>(means, opac, colors, scales, rots, bg, vm, out, n);
}